// round 3
// baseline (speedup 1.0000x reference)
#include <cuda_runtime.h>
#include <cuda_bf16.h>
#include <math.h>
#include <stdint.h>

// Problem constants
#define T_TOK   8192
#define DIMM    2048
#define NH      16
#define NKV     8
#define HD      128
#define SEQ     1024
#define BATCH   8
#define NREP    2

// ---------------- scratch (device globals; no allocations allowed) ----------------
__device__ float g_q[T_TOK * (size_t)(NH * HD)];     // 8192 x 2048
__device__ float g_k[T_TOK * (size_t)(NKV * HD)];    // 8192 x 1024
__device__ float g_v[T_TOK * (size_t)(NKV * HD)];    // 8192 x 1024
__device__ float g_attn[T_TOK * (size_t)(NH * HD)];  // 8192 x 2048
__device__ float g_cos[SEQ * 64];
__device__ float g_sin[SEQ * 64];

// ---------------- RoPE table ----------------
__global__ void rope_table_kernel() {
    int idx = blockIdx.x * blockDim.x + threadIdx.x;  // SEQ*64 = 65536
    if (idx >= SEQ * 64) return;
    int pos = idx >> 6;
    int f = idx & 63;
    double inv = pow(10000.0, -(double)f / 64.0);
    double ang = (double)pos * inv;
    g_cos[idx] = (float)cos(ang);
    g_sin[idx] = (float)sin(ang);
}

// ---------------- RoPE apply (interleaved pairs) ----------------
__global__ void rope_apply_kernel(float* __restrict__ buf, const int* __restrict__ positions, int heads) {
    int t = blockIdx.x;
    int pos = positions[t];
    int npairs = heads * 64;
    for (int i = threadIdx.x; i < npairs; i += blockDim.x) {
        int h = i >> 6;
        int f = i & 63;
        float c = g_cos[pos * 64 + f];
        float s = g_sin[pos * 64 + f];
        float* p = buf + (size_t)t * (heads * HD) + h * HD + 2 * f;
        float xr = p[0], xi = p[1];
        p[0] = xr * c - xi * s;
        p[1] = xr * s + xi * c;
    }
}

// ---------------- SGEMM: C[M,N] = A[M,K] @ B[K,N], all row-major fp32 ----------------
// BM=BN=128, BK=8, 256 threads, 8x8 microtile. M,N,K multiples of tile dims.
#define BM 128
#define BN 128
#define BKK 8
__global__ __launch_bounds__(256) void sgemm_kernel(const float* __restrict__ A,
                                                    const float* __restrict__ B,
                                                    float* __restrict__ C,
                                                    int M, int N, int K) {
    __shared__ float As[BKK][BM];
    __shared__ float Bs[BKK][BN];
    int tid = threadIdx.x;
    int crow = blockIdx.y * BM;
    int ccol = blockIdx.x * BN;

    int arow = tid >> 1;            // 0..127
    int acol = (tid & 1) * 4;       // 0 or 4
    int brow = tid >> 5;            // 0..7
    int bcol = (tid & 31) * 4;      // 0..124

    int tr = (tid >> 4) * 8;        // 0..120
    int tc = (tid & 15) * 8;        // 0..120

    float acc[8][8];
#pragma unroll
    for (int i = 0; i < 8; i++)
#pragma unroll
        for (int j = 0; j < 8; j++) acc[i][j] = 0.f;

    const float* Aptr = A + (size_t)crow * K;
    const float* Bptr = B + ccol;

    for (int k0 = 0; k0 < K; k0 += BKK) {
        float4 av = *(const float4*)(Aptr + (size_t)arow * K + k0 + acol);
        As[acol + 0][arow] = av.x;
        As[acol + 1][arow] = av.y;
        As[acol + 2][arow] = av.z;
        As[acol + 3][arow] = av.w;
        float4 bv = *(const float4*)(Bptr + (size_t)(k0 + brow) * N + bcol);
        *(float4*)&Bs[brow][bcol] = bv;
        __syncthreads();

#pragma unroll
        for (int kk = 0; kk < BKK; kk++) {
            float ar[8], br[8];
#pragma unroll
            for (int i = 0; i < 8; i++) ar[i] = As[kk][tr + i];
#pragma unroll
            for (int j = 0; j < 8; j++) br[j] = Bs[kk][tc + j];
#pragma unroll
            for (int i = 0; i < 8; i++)
#pragma unroll
                for (int j = 0; j < 8; j++) acc[i][j] += ar[i] * br[j];
        }
        __syncthreads();
    }

#pragma unroll
    for (int i = 0; i < 8; i++) {
#pragma unroll
        for (int j = 0; j < 8; j += 4) {
            float4 v = make_float4(acc[i][j], acc[i][j + 1], acc[i][j + 2], acc[i][j + 3]);
            *(float4*)(C + (size_t)(crow + tr + i) * N + ccol + tc + j) = v;
        }
    }
}

// ---------------- Flash-style causal attention ----------------
// grid: (B*NH, SEQ/32), block 128 threads. 32 query rows x 32 key cols per tile.
// Each group of 4 threads owns one query row; each thread holds 32 dims of q and acc.
__global__ __launch_bounds__(128) void attn_kernel(const float* __restrict__ qb,
                                                   const float* __restrict__ kb,
                                                   const float* __restrict__ vb,
                                                   float* __restrict__ ob) {
    const float scale = 0.08838834764831845f;  // 1/sqrt(128)
    int bh = blockIdx.x;
    int b = bh >> 4;
    int h = bh & 15;
    int kvh = h >> 1;
    int qt = blockIdx.y;  // 0..31

    int tid = threadIdx.x;
    int row = tid >> 2;   // 0..31
    int sub = tid & 3;    // 0..3

    __shared__ float Ks[32][HD];
    __shared__ float Vs[32][HD];

    int q_pos = qt * 32 + row;             // position within sequence
    int q_tok = b * SEQ + q_pos;           // global token

    float qreg[32];
    {
        const float* qp = qb + (size_t)q_tok * (NH * HD) + h * HD + sub * 32;
#pragma unroll
        for (int i = 0; i < 32; i++) qreg[i] = qp[i] * scale;
    }

    float acc[32];
#pragma unroll
    for (int i = 0; i < 32; i++) acc[i] = 0.f;
    float m = -INFINITY;
    float l = 0.f;

    for (int kt = 0; kt <= qt; kt++) {
        // cooperative load of K/V tiles: 32 rows x 128 floats = 1024 float4
        {
            int base_tok = b * SEQ + kt * 32;
#pragma unroll
            for (int j = 0; j < 8; j++) {
                int idx = tid + j * 128;       // 0..1023
                int r = idx >> 5;              // key row
                int c4 = idx & 31;             // float4 col
                const float4* ksrc = (const float4*)(kb + (size_t)(base_tok + r) * (NKV * HD) + kvh * HD + c4 * 4);
                const float4* vsrc = (const float4*)(vb + (size_t)(base_tok + r) * (NKV * HD) + kvh * HD + c4 * 4);
                *(float4*)&Ks[r][c4 * 4] = *ksrc;
                *(float4*)&Vs[r][c4 * 4] = *vsrc;
            }
        }
        __syncthreads();

        // partial dots over this thread's 32 dims, for all 32 keys
        float s[32];
#pragma unroll
        for (int n = 0; n < 32; n++) {
            float acc_d = 0.f;
            const float* krow = &Ks[n][sub * 32];
#pragma unroll
            for (int i = 0; i < 32; i++) acc_d += qreg[i] * krow[i];
            s[n] = acc_d;
        }
        // butterfly reduce across the 4 threads of the row group
#pragma unroll
        for (int n = 0; n < 32; n++) {
            s[n] += __shfl_xor_sync(0xffffffffu, s[n], 1);
            s[n] += __shfl_xor_sync(0xffffffffu, s[n], 2);
        }
        // causal mask on diagonal tile
        if (kt == qt) {
#pragma unroll
            for (int n = 0; n < 32; n++)
                if (kt * 32 + n > q_pos) s[n] = -INFINITY;
        }
        // online softmax
        float m_new = m;
#pragma unroll
        for (int n = 0; n < 32; n++) m_new = fmaxf(m_new, s[n]);
        float corr = __expf(m - m_new);
        float p[32];
        float psum = 0.f;
#pragma unroll
        for (int n = 0; n < 32; n++) {
            p[n] = __expf(s[n] - m_new);
            psum += p[n];
        }
        l = l * corr + psum;
#pragma unroll
        for (int i = 0; i < 32; i++) acc[i] *= corr;
#pragma unroll
        for (int n = 0; n < 32; n++) {
            float pn = p[n];
            const float* vrow = &Vs[n][sub * 32];
#pragma unroll
            for (int i = 0; i < 32; i++) acc[i] += pn * vrow[i];
        }
        m = m_new;
        __syncthreads();
    }

    float inv = 1.f / l;
    float* op = ob + (size_t)q_tok * (NH * HD) + h * HD + sub * 32;
#pragma unroll
    for (int i = 0; i < 32; i += 4) {
        float4 v = make_float4(acc[i] * inv, acc[i + 1] * inv, acc[i + 2] * inv, acc[i + 3] * inv);
        *(float4*)(op + i) = v;
    }
}

// ---------------- launch ----------------
extern "C" void kernel_launch(void* const* d_in, const int* in_sizes, int n_in,
                              void* d_out, int out_size) {
    const float* x  = (const float*)d_in[0];
    const float* wq = (const float*)d_in[1];
    const float* wk = (const float*)d_in[2];
    const float* wv = (const float*)d_in[3];
    const float* wo = (const float*)d_in[4];
    const int* positions = (const int*)d_in[7];
    float* out = (float*)d_out;

    float* qb; cudaGetSymbolAddress((void**)&qb, g_q);
    float* kb; cudaGetSymbolAddress((void**)&kb, g_k);
    float* vb; cudaGetSymbolAddress((void**)&vb, g_v);
    float* ab; cudaGetSymbolAddress((void**)&ab, g_attn);

    // RoPE table (recomputed every launch; deterministic)
    rope_table_kernel<<<(SEQ * 64 + 255) / 256, 256>>>();

    // QKV projections
    {
        dim3 gq(DIMM / BN, T_TOK / BM);
        sgemm_kernel<<<gq, 256>>>(x, wq, qb, T_TOK, DIMM, DIMM);
        dim3 gk((NKV * HD) / BN, T_TOK / BM);
        sgemm_kernel<<<gk, 256>>>(x, wk, kb, T_TOK, NKV * HD, DIMM);
        sgemm_kernel<<<gk, 256>>>(x, wv, vb, T_TOK, NKV * HD, DIMM);
    }

    // RoPE on Q and K
    rope_apply_kernel<<<T_TOK, 512>>>(qb, positions, NH);
    rope_apply_kernel<<<T_TOK, 512>>>(kb, positions, NKV);

    // causal attention
    {
        dim3 ga(BATCH * NH, SEQ / 32);
        attn_kernel<<<ga, 128>>>(qb, kb, vb, ab);
    }

    // output projection
    {
        dim3 go(DIMM / BN, T_TOK / BM);
        sgemm_kernel<<<go, 256>>>(ab, wo, out, T_TOK, DIMM, DIMM);
    }
}

// round 4
// speedup vs baseline: 6.1645x; 6.1645x over previous
#include <cuda_runtime.h>
#include <cuda_bf16.h>
#include <math.h>
#include <stdint.h>

// Problem constants
#define T_TOK   8192
#define DIMM    2048
#define NH      16
#define NKV     8
#define HD      128
#define SEQ     1024
#define BATCH   8

// ---------------- scratch (device globals) ----------------
__device__ float g_q[T_TOK * (size_t)(NH * HD)];     // 8192 x 2048
__device__ float g_k[T_TOK * (size_t)(NKV * HD)];    // 8192 x 1024
__device__ float g_v[T_TOK * (size_t)(NKV * HD)];    // 8192 x 1024
__device__ float g_attn[T_TOK * (size_t)(NH * HD)];  // 8192 x 2048
__device__ float g_cos[SEQ * 64];
__device__ float g_sin[SEQ * 64];

// ---------------- RoPE table ----------------
__global__ void rope_table_kernel() {
    int idx = blockIdx.x * blockDim.x + threadIdx.x;
    if (idx >= SEQ * 64) return;
    int pos = idx >> 6;
    int f = idx & 63;
    double inv = pow(10000.0, -(double)f / 64.0);
    double ang = (double)pos * inv;
    g_cos[idx] = (float)cos(ang);
    g_sin[idx] = (float)sin(ang);
}

// ---------------- RoPE apply ----------------
__global__ void rope_apply_kernel(float* __restrict__ buf, const int* __restrict__ positions, int heads) {
    int t = blockIdx.x;
    int pos = positions[t];
    int npairs = heads * 64;
    for (int i = threadIdx.x; i < npairs; i += blockDim.x) {
        int h = i >> 6;
        int f = i & 63;
        float c = g_cos[pos * 64 + f];
        float s = g_sin[pos * 64 + f];
        float* p = buf + (size_t)t * (heads * HD) + h * HD + 2 * f;
        float xr = p[0], xi = p[1];
        p[0] = xr * c - xi * s;
        p[1] = xr * s + xi * c;
    }
}

// ---------------- TF32 tensor-core GEMM ----------------
// C[M,N] = A[M,K] @ B[K,N], row-major fp32 in/out, tf32 mma accumulate fp32.
// BM=BN=128, BK=16, 256 threads = 8 warps (2x4), warp tile 64x32.
// smem stride 136 (8 mod 32) -> fragment loads are bank-conflict-free.
#define GST 136

__device__ __forceinline__ uint32_t f2tf(float x) {
    uint32_t r;
    asm("cvt.rna.tf32.f32 %0, %1;" : "=r"(r) : "f"(x));
    return r;
}

__global__ __launch_bounds__(256, 2) void tf32_gemm(const float* __restrict__ A,
                                                    const float* __restrict__ B,
                                                    float* __restrict__ C,
                                                    int M, int N, int K) {
    __shared__ uint32_t As[2][16][GST];
    __shared__ uint32_t Bs[2][16][GST];

    int tid = threadIdx.x;
    int warp = tid >> 5, lane = tid & 31;
    int wy = warp >> 2, wx = warp & 3;           // 2 x 4 warp grid
    int group = lane >> 2, tg = lane & 3;
    int bm = blockIdx.y * 128, bn = blockIdx.x * 128;

    // gmem load mapping
    int am = tid & 127;             // A row within tile
    int ak = (tid >> 7) * 4;        // A k-chunk: 0 or 4 (second chunk +8)
    int bk = tid >> 5;              // B k row: 0..7 (second +8)
    int bn4 = (tid & 31) * 4;       // B col chunk

    const float* Abase = A + (size_t)(bm + am) * K;
    const float* Bbase = B + bn + bn4;

    float4 av0, av1, bv0, bv1;
    av0 = *(const float4*)(Abase + ak);
    av1 = *(const float4*)(Abase + ak + 8);
    bv0 = *(const float4*)(Bbase + (size_t)bk * N);
    bv1 = *(const float4*)(Bbase + (size_t)(bk + 8) * N);

    float acc[4][4][4];
#pragma unroll
    for (int mt = 0; mt < 4; mt++)
#pragma unroll
        for (int nt = 0; nt < 4; nt++)
#pragma unroll
            for (int r = 0; r < 4; r++) acc[mt][nt][r] = 0.f;

    // stage tile 0
    As[0][ak + 0][am] = f2tf(av0.x);
    As[0][ak + 1][am] = f2tf(av0.y);
    As[0][ak + 2][am] = f2tf(av0.z);
    As[0][ak + 3][am] = f2tf(av0.w);
    As[0][ak + 8][am] = f2tf(av1.x);
    As[0][ak + 9][am] = f2tf(av1.y);
    As[0][ak + 10][am] = f2tf(av1.z);
    As[0][ak + 11][am] = f2tf(av1.w);
    {
        uint4 t0 = make_uint4(f2tf(bv0.x), f2tf(bv0.y), f2tf(bv0.z), f2tf(bv0.w));
        uint4 t1 = make_uint4(f2tf(bv1.x), f2tf(bv1.y), f2tf(bv1.z), f2tf(bv1.w));
        *(uint4*)&Bs[0][bk][bn4] = t0;
        *(uint4*)&Bs[0][bk + 8][bn4] = t1;
    }
    __syncthreads();

    int NT = K >> 4;
    int p = 0;
    for (int kt = 0; kt < NT; kt++) {
        if (kt + 1 < NT) {
            const float* Ap = Abase + (kt + 1) * 16;
            av0 = *(const float4*)(Ap + ak);
            av1 = *(const float4*)(Ap + ak + 8);
            const float* Bp = Bbase + (size_t)(kt + 1) * 16 * N;
            bv0 = *(const float4*)(Bp + (size_t)bk * N);
            bv1 = *(const float4*)(Bp + (size_t)(bk + 8) * N);
        }

#pragma unroll
        for (int ks = 0; ks < 2; ks++) {
            int k0 = ks * 8;
            uint32_t afr[4][4], bfr[4][2];
#pragma unroll
            for (int nt = 0; nt < 4; nt++) {
                int nb = wx * 32 + nt * 8 + group;
                bfr[nt][0] = Bs[p][k0 + tg][nb];
                bfr[nt][1] = Bs[p][k0 + tg + 4][nb];
            }
#pragma unroll
            for (int mt = 0; mt < 4; mt++) {
                int mb = wy * 64 + mt * 16 + group;
                afr[mt][0] = As[p][k0 + tg][mb];
                afr[mt][1] = As[p][k0 + tg][mb + 8];
                afr[mt][2] = As[p][k0 + tg + 4][mb];
                afr[mt][3] = As[p][k0 + tg + 4][mb + 8];
            }
#pragma unroll
            for (int mt = 0; mt < 4; mt++) {
#pragma unroll
                for (int nt = 0; nt < 4; nt++) {
                    asm volatile(
                        "mma.sync.aligned.m16n8k8.row.col.f32.tf32.tf32.f32 "
                        "{%0,%1,%2,%3}, {%4,%5,%6,%7}, {%8,%9}, {%0,%1,%2,%3};\n"
                        : "+f"(acc[mt][nt][0]), "+f"(acc[mt][nt][1]),
                          "+f"(acc[mt][nt][2]), "+f"(acc[mt][nt][3])
                        : "r"(afr[mt][0]), "r"(afr[mt][1]), "r"(afr[mt][2]), "r"(afr[mt][3]),
                          "r"(bfr[nt][0]), "r"(bfr[nt][1]));
                }
            }
        }

        if (kt + 1 < NT) {
            int q = p ^ 1;
            As[q][ak + 0][am] = f2tf(av0.x);
            As[q][ak + 1][am] = f2tf(av0.y);
            As[q][ak + 2][am] = f2tf(av0.z);
            As[q][ak + 3][am] = f2tf(av0.w);
            As[q][ak + 8][am] = f2tf(av1.x);
            As[q][ak + 9][am] = f2tf(av1.y);
            As[q][ak + 10][am] = f2tf(av1.z);
            As[q][ak + 11][am] = f2tf(av1.w);
            uint4 t0 = make_uint4(f2tf(bv0.x), f2tf(bv0.y), f2tf(bv0.z), f2tf(bv0.w));
            uint4 t1 = make_uint4(f2tf(bv1.x), f2tf(bv1.y), f2tf(bv1.z), f2tf(bv1.w));
            *(uint4*)&Bs[q][bk][bn4] = t0;
            *(uint4*)&Bs[q][bk + 8][bn4] = t1;
        }
        __syncthreads();
        p ^= 1;
    }

    // epilogue
#pragma unroll
    for (int mt = 0; mt < 4; mt++) {
#pragma unroll
        for (int nt = 0; nt < 4; nt++) {
            int row = bm + wy * 64 + mt * 16 + group;
            int col = bn + wx * 32 + nt * 8 + tg * 2;
            float2 v01 = make_float2(acc[mt][nt][0], acc[mt][nt][1]);
            float2 v23 = make_float2(acc[mt][nt][2], acc[mt][nt][3]);
            *(float2*)(C + (size_t)row * N + col) = v01;
            *(float2*)(C + (size_t)(row + 8) * N + col) = v23;
        }
    }
}

// ---------------- Flash attention, register-tiled fp32 ----------------
// Block: 256 threads, Q tile 128 rows, key tile 64.
// Score phase: thread (ty=tid/16, tx=tid%16): 8 q rows (ty*8+i) x 4 keys (tx+16j).
// PV phase: same rows x 8 d-cols (tx+16j). All smem reads broadcast or conflict-free.
#define QS_ST 132   // Qs stride (16B aligned)
#define KS_ST 129   // Ks/Vs stride (odd -> conflict-free strided reads)
#define PS_ST 66    // Ps stride

__global__ __launch_bounds__(256, 1) void attn2_kernel(const float* __restrict__ qb,
                                                       const float* __restrict__ kb,
                                                       const float* __restrict__ vb,
                                                       float* __restrict__ ob) {
    extern __shared__ float sm[];
    float* Qs = sm;                          // 128 x 132
    float* Ks = Qs + 128 * QS_ST;            // 64 x 129
    float* Vs = Ks + 64 * KS_ST;             // 64 x 129
    float* Ps = Vs + 64 * KS_ST;             // 128 x 66

    const float scale = 0.08838834764831845f;
    int bh = blockIdx.x;
    int b = bh >> 4;
    int h = bh & 15;
    int kvh = h >> 1;
    int qt = blockIdx.y;                     // 0..7

    int tid = threadIdx.x;
    int ty = tid >> 4;                       // 0..15
    int tx = tid & 15;                       // 0..15

    // fill Q tile (scaled)
    for (int idx = tid; idx < 128 * 32; idx += 256) {
        int r = idx >> 5;
        int c4 = (idx & 31) * 4;
        const float4 v = *(const float4*)(qb + (size_t)((b << 10) + (qt << 7) + r) * (NH * HD) + (h << 7) + c4);
        float4 w = make_float4(v.x * scale, v.y * scale, v.z * scale, v.w * scale);
        *(float4*)&Qs[r * QS_ST + c4] = w;
    }

    float O[8][8];
#pragma unroll
    for (int i = 0; i < 8; i++)
#pragma unroll
        for (int j = 0; j < 8; j++) O[i][j] = 0.f;
    float mrow[8], lrow[8];
#pragma unroll
    for (int i = 0; i < 8; i++) { mrow[i] = -INFINITY; lrow[i] = 0.f; }

    int ntiles = 2 * qt + 2;
    for (int kt = 0; kt < ntiles; kt++) {
        // fill K/V tiles
        for (int idx = tid; idx < 64 * 32; idx += 256) {
            int r = idx >> 5;
            int c4 = (idx & 31) * 4;
            size_t base = (size_t)((b << 10) + (kt << 6) + r) * (NKV * HD) + (kvh << 7) + c4;
            float4 kv = *(const float4*)(kb + base);
            float4 vv = *(const float4*)(vb + base);
            Ks[r * KS_ST + c4 + 0] = kv.x; Ks[r * KS_ST + c4 + 1] = kv.y;
            Ks[r * KS_ST + c4 + 2] = kv.z; Ks[r * KS_ST + c4 + 3] = kv.w;
            Vs[r * KS_ST + c4 + 0] = vv.x; Vs[r * KS_ST + c4 + 1] = vv.y;
            Vs[r * KS_ST + c4 + 2] = vv.z; Vs[r * KS_ST + c4 + 3] = vv.w;
        }
        __syncthreads();

        // scores: s[i][j] = q(row ty*8+i) . k(key tx+16j)
        float s[8][4];
#pragma unroll
        for (int i = 0; i < 8; i++)
#pragma unroll
            for (int j = 0; j < 4; j++) s[i][j] = 0.f;

#pragma unroll 4
        for (int d = 0; d < 128; d++) {
            float qv[8], kv[4];
#pragma unroll
            for (int i = 0; i < 8; i++) qv[i] = Qs[(ty * 8 + i) * QS_ST + d];
#pragma unroll
            for (int j = 0; j < 4; j++) kv[j] = Ks[(tx + 16 * j) * KS_ST + d];
#pragma unroll
            for (int i = 0; i < 8; i++)
#pragma unroll
                for (int j = 0; j < 4; j++) s[i][j] += qv[i] * kv[j];
        }

        // causal mask on diagonal tiles
        if (kt >= 2 * qt) {
#pragma unroll
            for (int i = 0; i < 8; i++) {
                int qp = qt * 128 + ty * 8 + i;
#pragma unroll
                for (int j = 0; j < 4; j++) {
                    int kp = kt * 64 + tx + 16 * j;
                    if (kp > qp) s[i][j] = -INFINITY;
                }
            }
        }

        // online softmax (rows owned by 16-lane groups)
#pragma unroll
        for (int i = 0; i < 8; i++) {
            float tm = s[i][0];
#pragma unroll
            for (int j = 1; j < 4; j++) tm = fmaxf(tm, s[i][j]);
            tm = fmaxf(tm, __shfl_xor_sync(0xffffffffu, tm, 1));
            tm = fmaxf(tm, __shfl_xor_sync(0xffffffffu, tm, 2));
            tm = fmaxf(tm, __shfl_xor_sync(0xffffffffu, tm, 4));
            tm = fmaxf(tm, __shfl_xor_sync(0xffffffffu, tm, 8));
            float m_new = fmaxf(mrow[i], tm);
            float corr = __expf(mrow[i] - m_new);
            float psum = 0.f;
#pragma unroll
            for (int j = 0; j < 4; j++) {
                float pv = __expf(s[i][j] - m_new);
                Ps[(ty * 8 + i) * PS_ST + tx + 16 * j] = pv;
                psum += pv;
            }
            psum += __shfl_xor_sync(0xffffffffu, psum, 1);
            psum += __shfl_xor_sync(0xffffffffu, psum, 2);
            psum += __shfl_xor_sync(0xffffffffu, psum, 4);
            psum += __shfl_xor_sync(0xffffffffu, psum, 8);
            lrow[i] = lrow[i] * corr + psum;
            mrow[i] = m_new;
#pragma unroll
            for (int j = 0; j < 8; j++) O[i][j] *= corr;
        }
        __syncthreads();

        // PV: O[i][j] += sum_k P(row, k) * V(k, col tx+16j)
#pragma unroll 4
        for (int k = 0; k < 64; k++) {
            float pr[8], vr[8];
#pragma unroll
            for (int i = 0; i < 8; i++) pr[i] = Ps[(ty * 8 + i) * PS_ST + k];
#pragma unroll
            for (int j = 0; j < 8; j++) vr[j] = Vs[k * KS_ST + tx + 16 * j];
#pragma unroll
            for (int i = 0; i < 8; i++)
#pragma unroll
                for (int j = 0; j < 8; j++) O[i][j] += pr[i] * vr[j];
        }
        __syncthreads();
    }

    // write out
#pragma unroll
    for (int i = 0; i < 8; i++) {
        float inv = 1.f / lrow[i];
        int tok = (b << 10) + (qt << 7) + ty * 8 + i;
        float* op = ob + (size_t)tok * (NH * HD) + (h << 7);
#pragma unroll
        for (int j = 0; j < 8; j++) op[tx + 16 * j] = O[i][j] * inv;
    }
}

// ---------------- launch ----------------
extern "C" void kernel_launch(void* const* d_in, const int* in_sizes, int n_in,
                              void* d_out, int out_size) {
    const float* x  = (const float*)d_in[0];
    const float* wq = (const float*)d_in[1];
    const float* wk = (const float*)d_in[2];
    const float* wv = (const float*)d_in[3];
    const float* wo = (const float*)d_in[4];
    const int* positions = (const int*)d_in[7];
    float* out = (float*)d_out;

    float* qb; cudaGetSymbolAddress((void**)&qb, g_q);
    float* kb; cudaGetSymbolAddress((void**)&kb, g_k);
    float* vb; cudaGetSymbolAddress((void**)&vb, g_v);
    float* ab; cudaGetSymbolAddress((void**)&ab, g_attn);

    rope_table_kernel<<<(SEQ * 64 + 255) / 256, 256>>>();

    // QKV projections (tf32 tensor cores)
    {
        dim3 gq(DIMM / 128, T_TOK / 128);
        tf32_gemm<<<gq, 256>>>(x, wq, qb, T_TOK, DIMM, DIMM);
        dim3 gk((NKV * HD) / 128, T_TOK / 128);
        tf32_gemm<<<gk, 256>>>(x, wk, kb, T_TOK, NKV * HD, DIMM);
        tf32_gemm<<<gk, 256>>>(x, wv, vb, T_TOK, NKV * HD, DIMM);
    }

    rope_apply_kernel<<<T_TOK, 512>>>(qb, positions, NH);
    rope_apply_kernel<<<T_TOK, 512>>>(kb, positions, NKV);

    // attention
    {
        size_t smem = (size_t)(128 * QS_ST + 64 * KS_ST * 2 + 128 * PS_ST) * sizeof(float);
        cudaFuncSetAttribute(attn2_kernel, cudaFuncAttributeMaxDynamicSharedMemorySize, (int)smem);
        dim3 ga(BATCH * NH, SEQ / 128);
        attn2_kernel<<<ga, 256, smem>>>(qb, kb, vb, ab);
    }

    // output projection
    {
        dim3 go(DIMM / 128, T_TOK / 128);
        tf32_gemm<<<go, 256>>>(ab, wo, out, T_TOK, DIMM, DIMM);
    }
}

// round 6
// speedup vs baseline: 7.7385x; 1.2553x over previous
#include <cuda_runtime.h>
#include <cuda_bf16.h>
#include <math.h>
#include <stdint.h>

// Problem constants
#define T_TOK   8192
#define DIMM    2048
#define NH      16
#define NKV     8
#define HD      128
#define SEQ     1024
#define BATCH   8

// ---------------- scratch (device globals) ----------------
__device__ float g_q[T_TOK * (size_t)(NH * HD)];     // 8192 x 2048
__device__ float g_k[T_TOK * (size_t)(NKV * HD)];    // 8192 x 1024
__device__ float g_v[T_TOK * (size_t)(NKV * HD)];    // 8192 x 1024
__device__ float g_attn[T_TOK * (size_t)(NH * HD)];  // 8192 x 2048
__device__ float g_cos[SEQ * 64];
__device__ float g_sin[SEQ * 64];

__device__ __forceinline__ uint32_t f2tf(float x) {
    uint32_t r;
    asm("cvt.rna.tf32.f32 %0, %1;" : "=r"(r) : "f"(x));
    return r;
}

__device__ __forceinline__ void mma_tf32(float* c,
                                         uint32_t a0, uint32_t a1, uint32_t a2, uint32_t a3,
                                         uint32_t b0, uint32_t b1) {
    asm volatile(
        "mma.sync.aligned.m16n8k8.row.col.f32.tf32.tf32.f32 "
        "{%0,%1,%2,%3}, {%4,%5,%6,%7}, {%8,%9}, {%0,%1,%2,%3};\n"
        : "+f"(c[0]), "+f"(c[1]), "+f"(c[2]), "+f"(c[3])
        : "r"(a0), "r"(a1), "r"(a2), "r"(a3), "r"(b0), "r"(b1));
}

// ---------------- RoPE table ----------------
__global__ void rope_table_kernel() {
    int idx = blockIdx.x * blockDim.x + threadIdx.x;
    if (idx >= SEQ * 64) return;
    int pos = idx >> 6;
    int f = idx & 63;
    double inv = pow(10000.0, -(double)f / 64.0);
    double ang = (double)pos * inv;
    g_cos[idx] = (float)cos(ang);
    g_sin[idx] = (float)sin(ang);
}

// ---------------- RoPE apply ----------------
__global__ void rope_apply_kernel(float* __restrict__ buf, const int* __restrict__ positions, int heads) {
    int t = blockIdx.x;
    int pos = positions[t];
    int npairs = heads * 64;
    for (int i = threadIdx.x; i < npairs; i += blockDim.x) {
        int h = i >> 6;
        int f = i & 63;
        float c = g_cos[pos * 64 + f];
        float s = g_sin[pos * 64 + f];
        float* p = buf + (size_t)t * (heads * HD) + h * HD + 2 * f;
        float xr = p[0], xi = p[1];
        p[0] = xr * c - xi * s;
        p[1] = xr * s + xi * c;
    }
}

// ---------------- TF32 tensor-core GEMM (validated R4) ----------------
#define GST 136

__global__ __launch_bounds__(256, 2) void tf32_gemm(const float* __restrict__ A,
                                                    const float* __restrict__ B,
                                                    float* __restrict__ C,
                                                    int M, int N, int K) {
    __shared__ uint32_t As[2][16][GST];
    __shared__ uint32_t Bs[2][16][GST];

    int tid = threadIdx.x;
    int warp = tid >> 5, lane = tid & 31;
    int wy = warp >> 2, wx = warp & 3;
    int group = lane >> 2, tg = lane & 3;
    int bm = blockIdx.y * 128, bn = blockIdx.x * 128;

    int am = tid & 127;
    int ak = (tid >> 7) * 4;
    int bk = tid >> 5;
    int bn4 = (tid & 31) * 4;

    const float* Abase = A + (size_t)(bm + am) * K;
    const float* Bbase = B + bn + bn4;

    float4 av0, av1, bv0, bv1;
    av0 = *(const float4*)(Abase + ak);
    av1 = *(const float4*)(Abase + ak + 8);
    bv0 = *(const float4*)(Bbase + (size_t)bk * N);
    bv1 = *(const float4*)(Bbase + (size_t)(bk + 8) * N);

    float acc[4][4][4];
#pragma unroll
    for (int mt = 0; mt < 4; mt++)
#pragma unroll
        for (int nt = 0; nt < 4; nt++)
#pragma unroll
            for (int r = 0; r < 4; r++) acc[mt][nt][r] = 0.f;

    As[0][ak + 0][am] = f2tf(av0.x);
    As[0][ak + 1][am] = f2tf(av0.y);
    As[0][ak + 2][am] = f2tf(av0.z);
    As[0][ak + 3][am] = f2tf(av0.w);
    As[0][ak + 8][am] = f2tf(av1.x);
    As[0][ak + 9][am] = f2tf(av1.y);
    As[0][ak + 10][am] = f2tf(av1.z);
    As[0][ak + 11][am] = f2tf(av1.w);
    {
        uint4 t0 = make_uint4(f2tf(bv0.x), f2tf(bv0.y), f2tf(bv0.z), f2tf(bv0.w));
        uint4 t1 = make_uint4(f2tf(bv1.x), f2tf(bv1.y), f2tf(bv1.z), f2tf(bv1.w));
        *(uint4*)&Bs[0][bk][bn4] = t0;
        *(uint4*)&Bs[0][bk + 8][bn4] = t1;
    }
    __syncthreads();

    int NT = K >> 4;
    int p = 0;
    for (int kt = 0; kt < NT; kt++) {
        if (kt + 1 < NT) {
            const float* Ap = Abase + (kt + 1) * 16;
            av0 = *(const float4*)(Ap + ak);
            av1 = *(const float4*)(Ap + ak + 8);
            const float* Bp = Bbase + (size_t)(kt + 1) * 16 * N;
            bv0 = *(const float4*)(Bp + (size_t)bk * N);
            bv1 = *(const float4*)(Bp + (size_t)(bk + 8) * N);
        }

#pragma unroll
        for (int ks = 0; ks < 2; ks++) {
            int k0 = ks * 8;
            uint32_t afr[4][4], bfr[4][2];
#pragma unroll
            for (int nt = 0; nt < 4; nt++) {
                int nb = wx * 32 + nt * 8 + group;
                bfr[nt][0] = Bs[p][k0 + tg][nb];
                bfr[nt][1] = Bs[p][k0 + tg + 4][nb];
            }
#pragma unroll
            for (int mt = 0; mt < 4; mt++) {
                int mb = wy * 64 + mt * 16 + group;
                afr[mt][0] = As[p][k0 + tg][mb];
                afr[mt][1] = As[p][k0 + tg][mb + 8];
                afr[mt][2] = As[p][k0 + tg + 4][mb];
                afr[mt][3] = As[p][k0 + tg + 4][mb + 8];
            }
#pragma unroll
            for (int mt = 0; mt < 4; mt++)
#pragma unroll
                for (int nt = 0; nt < 4; nt++)
                    mma_tf32(acc[mt][nt], afr[mt][0], afr[mt][1], afr[mt][2], afr[mt][3],
                             bfr[nt][0], bfr[nt][1]);
        }

        if (kt + 1 < NT) {
            int q = p ^ 1;
            As[q][ak + 0][am] = f2tf(av0.x);
            As[q][ak + 1][am] = f2tf(av0.y);
            As[q][ak + 2][am] = f2tf(av0.z);
            As[q][ak + 3][am] = f2tf(av0.w);
            As[q][ak + 8][am] = f2tf(av1.x);
            As[q][ak + 9][am] = f2tf(av1.y);
            As[q][ak + 10][am] = f2tf(av1.z);
            As[q][ak + 11][am] = f2tf(av1.w);
            uint4 t0 = make_uint4(f2tf(bv0.x), f2tf(bv0.y), f2tf(bv0.z), f2tf(bv0.w));
            uint4 t1 = make_uint4(f2tf(bv1.x), f2tf(bv1.y), f2tf(bv1.z), f2tf(bv1.w));
            *(uint4*)&Bs[q][bk][bn4] = t0;
            *(uint4*)&Bs[q][bk + 8][bn4] = t1;
        }
        __syncthreads();
        p ^= 1;
    }

#pragma unroll
    for (int mt = 0; mt < 4; mt++) {
#pragma unroll
        for (int nt = 0; nt < 4; nt++) {
            int row = bm + wy * 64 + mt * 16 + group;
            int col = bn + wx * 32 + nt * 8 + tg * 2;
            float2 v01 = make_float2(acc[mt][nt][0], acc[mt][nt][1]);
            float2 v23 = make_float2(acc[mt][nt][2], acc[mt][nt][3]);
            *(float2*)(C + (size_t)row * N + col) = v01;
            *(float2*)(C + (size_t)(row + 8) * N + col) = v23;
        }
    }
}

// ---------------- Flash attention on TF32 tensor cores (warp-owns-rows) ----------------
// Q tile 128 x 128, key tile 64. 256 threads = 8 warps; warp w owns q rows [16w,16w+16).
// Scores: per warp 16x64 = 1 m-tile x 8 n-tiles (m16n8k8).
// PV:     per warp 16 rows x 128 dims = 1 m-tile x 16 n-tiles.
// Softmax stats are warp-private per row (full 64-key coverage per warp).
// smem row strides mod 32: Q/K 132->4, V 136->8, P 68->4 => all fragment LDS conflict-free.
#define AT_QST 132
#define AT_KST 132
#define AT_VST 136
#define AT_PST 68
#define AT_SMEM_WORDS (128*AT_QST + 64*AT_KST + 64*AT_VST + 128*AT_PST)

__global__ __launch_bounds__(256, 1) void attn4_kernel(const float* __restrict__ qb,
                                                       const float* __restrict__ kb,
                                                       const float* __restrict__ vb,
                                                       float* __restrict__ ob) {
    extern __shared__ uint32_t smw[];
    uint32_t* Qs = smw;                       // [128][132]
    uint32_t* Ks = Qs + 128 * AT_QST;         // [64][132]
    uint32_t* Vs = Ks + 64 * AT_KST;          // [64][136]
    uint32_t* Ps = Vs + 64 * AT_VST;          // [128][68]

    const float scale = 0.08838834764831845f;
    int qt = 7 - blockIdx.x;                  // heavy tiles first
    int bh = blockIdx.y;
    int b = bh >> 4;
    int h = bh & 15;
    int kvh = h >> 1;

    int tid = threadIdx.x;
    int warp = tid >> 5, lane = tid & 31;
    int group = lane >> 2, tg = lane & 3;
    int mrow0 = warp * 16;                    // this warp's first q row in tile

    // stage Q (scaled, tf32)
    for (int idx = tid; idx < 128 * 32; idx += 256) {
        int r = idx >> 5;
        int c4 = (idx & 31) * 4;
        float4 v = *(const float4*)(qb + (size_t)((b << 10) + (qt << 7) + r) * (NH * HD) + (h << 7) + c4);
        uint4 w = make_uint4(f2tf(v.x * scale), f2tf(v.y * scale), f2tf(v.z * scale), f2tf(v.w * scale));
        *(uint4*)&Qs[r * AT_QST + c4] = w;
    }

    float Oacc[16][4];
#pragma unroll
    for (int ot = 0; ot < 16; ot++)
#pragma unroll
        for (int r = 0; r < 4; r++) Oacc[ot][r] = 0.f;
    float mrow[2] = {-INFINITY, -INFINITY};
    float lrow[2] = {0.f, 0.f};

    int ntiles = 2 * qt + 2;
    for (int kt = 0; kt < ntiles; kt++) {
        __syncthreads();  // Ks/Vs reads of prev iter done (also orders Q staging on iter 0)

        // stage K/V (tf32), coalesced
        for (int idx = tid; idx < 64 * 32; idx += 256) {
            int r = idx >> 5;
            int c4 = (idx & 31) * 4;
            size_t base = (size_t)((b << 10) + (kt << 6) + r) * (NKV * HD) + (kvh << 7) + c4;
            float4 kv = *(const float4*)(kb + base);
            float4 vv = *(const float4*)(vb + base);
            *(uint4*)&Ks[r * AT_KST + c4] = make_uint4(f2tf(kv.x), f2tf(kv.y), f2tf(kv.z), f2tf(kv.w));
            *(uint4*)&Vs[r * AT_VST + c4] = make_uint4(f2tf(vv.x), f2tf(vv.y), f2tf(vv.z), f2tf(vv.w));
        }
        __syncthreads();

        // warp entirely above the causal frontier for this key tile -> skip
        bool active = (kt << 6) <= (qt << 7) + mrow0 + 15;
        if (active) {
            // ---- scores: S(16x64) = Q_rows @ K^T ----
            float sacc[8][4];
#pragma unroll
            for (int nt = 0; nt < 8; nt++)
#pragma unroll
                for (int r = 0; r < 4; r++) sacc[nt][r] = 0.f;

#pragma unroll 4
            for (int ks = 0; ks < 16; ks++) {
                int k0 = ks * 8;
                const uint32_t* qr = Qs + (mrow0 + group) * AT_QST + k0 + tg;
                uint32_t a0 = qr[0];
                uint32_t a1 = qr[8 * AT_QST];
                uint32_t a2 = qr[4];
                uint32_t a3 = qr[8 * AT_QST + 4];
#pragma unroll
                for (int nt = 0; nt < 8; nt++) {
                    const uint32_t* kr = Ks + (nt * 8 + group) * AT_KST + k0 + tg;
                    mma_tf32(sacc[nt], a0, a1, a2, a3, kr[0], kr[4]);
                }
            }

            // causal mask (diagonal super-tiles only)
            if (kt >= 2 * qt) {
                int qp = (qt << 7) + mrow0 + group;
#pragma unroll
                for (int nt = 0; nt < 8; nt++) {
                    int kp = (kt << 6) + nt * 8 + 2 * tg;
                    if (kp > qp) sacc[nt][0] = -INFINITY;
                    if (kp + 1 > qp) sacc[nt][1] = -INFINITY;
                    if (kp > qp + 8) sacc[nt][2] = -INFINITY;
                    if (kp + 1 > qp + 8) sacc[nt][3] = -INFINITY;
                }
            }

            // ---- online softmax (fp32, warp-private rows) + write P (tf32) ----
#pragma unroll
            for (int hf = 0; hf < 2; hf++) {
                float tm = -INFINITY;
#pragma unroll
                for (int nt = 0; nt < 8; nt++) {
                    tm = fmaxf(tm, sacc[nt][2 * hf]);
                    tm = fmaxf(tm, sacc[nt][2 * hf + 1]);
                }
                tm = fmaxf(tm, __shfl_xor_sync(0xffffffffu, tm, 1));
                tm = fmaxf(tm, __shfl_xor_sync(0xffffffffu, tm, 2));
                float mn = fmaxf(mrow[hf], tm);
                float corr = __expf(mrow[hf] - mn);
                float ps = 0.f;
                int row = mrow0 + group + hf * 8;
#pragma unroll
                for (int nt = 0; nt < 8; nt++) {
                    float p0 = __expf(sacc[nt][2 * hf] - mn);
                    float p1 = __expf(sacc[nt][2 * hf + 1] - mn);
                    ps += p0 + p1;
                    *(uint2*)&Ps[row * AT_PST + nt * 8 + 2 * tg] = make_uint2(f2tf(p0), f2tf(p1));
                }
                ps += __shfl_xor_sync(0xffffffffu, ps, 1);
                ps += __shfl_xor_sync(0xffffffffu, ps, 2);
                lrow[hf] = lrow[hf] * corr + ps;
                mrow[hf] = mn;
#pragma unroll
                for (int ot = 0; ot < 16; ot++) {
                    Oacc[ot][2 * hf] *= corr;
                    Oacc[ot][2 * hf + 1] *= corr;
                }
            }
            __syncwarp();  // P rows are warp-private: warp-level sync suffices

            // ---- PV: O(16x128) += P(16x64) @ V(64x128) ----
#pragma unroll 2
            for (int ks = 0; ks < 8; ks++) {
                int k0 = ks * 8;
                const uint32_t* pr = Ps + (mrow0 + group) * AT_PST + k0 + tg;
                uint32_t a0 = pr[0];
                uint32_t a1 = pr[8 * AT_PST];
                uint32_t a2 = pr[4];
                uint32_t a3 = pr[8 * AT_PST + 4];
#pragma unroll
                for (int ot = 0; ot < 16; ot++) {
                    const uint32_t* vr = Vs + (k0 + tg) * AT_VST + ot * 8 + group;
                    mma_tf32(Oacc[ot], a0, a1, a2, a3, vr[0], vr[4 * AT_VST]);
                }
            }
        }
    }

    // ---- write out ----
    {
        int r0 = mrow0 + group;
        float inv0 = 1.f / lrow[0];
        float inv1 = 1.f / lrow[1];
        int tok0 = (b << 10) + (qt << 7) + r0;
#pragma unroll
        for (int ot = 0; ot < 16; ot++) {
            int col = ot * 8 + 2 * tg;
            float2 v01 = make_float2(Oacc[ot][0] * inv0, Oacc[ot][1] * inv0);
            float2 v23 = make_float2(Oacc[ot][2] * inv1, Oacc[ot][3] * inv1);
            *(float2*)(ob + (size_t)tok0 * (NH * HD) + (h << 7) + col) = v01;
            *(float2*)(ob + (size_t)(tok0 + 8) * (NH * HD) + (h << 7) + col) = v23;
        }
    }
}

// ---------------- launch ----------------
extern "C" void kernel_launch(void* const* d_in, const int* in_sizes, int n_in,
                              void* d_out, int out_size) {
    const float* x  = (const float*)d_in[0];
    const float* wq = (const float*)d_in[1];
    const float* wk = (const float*)d_in[2];
    const float* wv = (const float*)d_in[3];
    const float* wo = (const float*)d_in[4];
    const int* positions = (const int*)d_in[7];
    float* out = (float*)d_out;

    float* qb; cudaGetSymbolAddress((void**)&qb, g_q);
    float* kb; cudaGetSymbolAddress((void**)&kb, g_k);
    float* vb; cudaGetSymbolAddress((void**)&vb, g_v);
    float* ab; cudaGetSymbolAddress((void**)&ab, g_attn);

    rope_table_kernel<<<(SEQ * 64 + 255) / 256, 256>>>();

    // QKV projections (tf32 tensor cores)
    {
        dim3 gq(DIMM / 128, T_TOK / 128);
        tf32_gemm<<<gq, 256>>>(x, wq, qb, T_TOK, DIMM, DIMM);
        dim3 gk((NKV * HD) / 128, T_TOK / 128);
        tf32_gemm<<<gk, 256>>>(x, wk, kb, T_TOK, NKV * HD, DIMM);
        tf32_gemm<<<gk, 256>>>(x, wv, vb, T_TOK, NKV * HD, DIMM);
    }

    rope_apply_kernel<<<T_TOK, 512>>>(qb, positions, NH);
    rope_apply_kernel<<<T_TOK, 512>>>(kb, positions, NKV);

    // attention (tf32 tensor cores)
    {
        size_t smem = (size_t)AT_SMEM_WORDS * sizeof(uint32_t);  // ~171 KB
        cudaFuncSetAttribute(attn4_kernel, cudaFuncAttributeMaxDynamicSharedMemorySize, (int)smem);
        dim3 ga(8, BATCH * NH);
        attn4_kernel<<<ga, 256, smem>>>(qb, kb, vb, ab);
    }

    // output projection
    {
        dim3 go(DIMM / 128, T_TOK / 128);
        tf32_gemm<<<go, 256>>>(ab, wo, out, T_TOK, DIMM, DIMM);
    }
}